// round 2
// baseline (speedup 1.0000x reference)
#include <cuda_runtime.h>
#include <cstring>

#define N_NODES   131072
#define N_GRAPHS  2048

// ---------------- scratch (static device globals; no allocs) ----------------
__device__ float d_msg[N_NODES * 10];
__device__ float d_deg[N_NODES];
__device__ float d_z[N_GRAPHS * 900];
__device__ float d_s1[N_GRAPHS * 100 * 200];
__device__ float d_s2[N_GRAPHS * 100 * 67];
__device__ float d_s3[N_GRAPHS * 100 * 23];
__device__ float d_bnsum[1800];
__device__ float d_sc[1800];       // [0..899]=scale, [900..1799]=shift
__device__ float d_W1p[900 * 256]; // folded fc1 weights, [j][i] transposed
__device__ float d_b1p[256];
__device__ float d_o1[N_GRAPHS * 256];
__device__ float d_o2[N_GRAPHS * 64];

// packed f32x2 FMA (Blackwell FFMA2; 2x fp32 throughput vs 3-reg FFMA)
__device__ __forceinline__ float2 ffma2(float2 a, float2 b, float2 c) {
    unsigned long long au, bu, cu, du;
    memcpy(&au, &a, 8); memcpy(&bu, &b, 8); memcpy(&cu, &c, 8);
    asm("fma.rn.f32x2 %0, %1, %2, %3;" : "=l"(du) : "l"(au), "l"(bu), "l"(cu));
    float2 d; memcpy(&d, &du, 8); return d;
}

// ---------------- zero scratch ----------------
__global__ void __launch_bounds__(256) zero_k() {
    unsigned int i = blockIdx.x * 256u + threadIdx.x;
    if (i < N_NODES * 10) d_msg[i] = 0.f;
    if (i < N_NODES)      d_deg[i] = 0.f;
    if (i < 1800)         d_bnsum[i] = 0.f;
}

// ---------------- edge scatter: msg_sum[dst] += x1[src], deg[dst] += 1 ----------------
__global__ void __launch_bounds__(256) edge_k(const float* __restrict__ x1,
                                              const int* __restrict__ ei, int nE) {
    int e = blockIdx.x * 256 + threadIdx.x;
    if (e >= nE) return;
    int s = ei[e], d = ei[nE + e];
    atomicAdd(&d_deg[d], 1.f);
    const float2* xs = (const float2*)(x1 + (size_t)s * 10);
    float* m = d_msg + (size_t)d * 10;
#pragma unroll
    for (int f = 0; f < 5; f++) {
        float2 v = xs[f];
        atomicAdd(&m[2 * f], v.x);
        atomicAdd(&m[2 * f + 1], v.y);
    }
}

// ---------------- graph branch: per-graph sums, then tiny GEMV into z[:, 0:100] ----------
// g = (sum_nodes mean_agg) @ Wl^T + 64*bl + (sum_nodes x1) @ Wr^T  (linearity of pooling)
__global__ void __launch_bounds__(128) gpool_k(const float* __restrict__ x1,
                                               const float* __restrict__ Wl,
                                               const float* __restrict__ bl,
                                               const float* __restrict__ Wr) {
    __shared__ float sm_[10], sx_[10];
    int g = blockIdx.x, tid = threadIdx.x;
    if (tid < 10) { sm_[tid] = 0.f; sx_[tid] = 0.f; }
    __syncthreads();
    if (tid < 64) {
        int n = g * 64 + tid;
        float inv = 1.f / fmaxf(d_deg[n], 1.f);
#pragma unroll
        for (int f = 0; f < 10; f++) {
            atomicAdd(&sm_[f], d_msg[(size_t)n * 10 + f] * inv);
            atomicAdd(&sx_[f], x1[(size_t)n * 10 + f]);
        }
    }
    __syncthreads();
    if (tid < 100) {
        float acc = 64.f * bl[tid];
#pragma unroll
        for (int f = 0; f < 10; f++)
            acc += sm_[f] * Wl[tid * 10 + f] + sx_[f] * Wr[tid * 10 + f];
        d_z[(size_t)g * 900 + tid] = acc;
    }
}

// ---------------- fused conv1d(same,k=3) + leakyReLU + maxpool3(stride3) ----------------
// Item = 4 out-channels x 2 pooled positions. Weights in smem transposed to
// [ci][k][co] so a single LDS.128 yields the 4-channel weight quad (= 2 float2
// pairs for FFMA2). Accumulate 6 conv positions as channel-paired float2.
template <int CIN, int LIN, int LPOOL, int PPAD, int OPITCH>
__global__ void __launch_bounds__(256) conv_k(const float* __restrict__ gin,
                                              const float* __restrict__ gw,
                                              const float* __restrict__ gb,
                                              float* __restrict__ gout) {
    extern __shared__ float shm[];
    float* s_in = shm;                 // CIN*LIN
    float* s_w  = shm + CIN * LIN;     // CIN*3*100 (transposed), 16B aligned
    float* s_b  = s_w + CIN * 300;     // 100
    const int g = blockIdx.x, tid = threadIdx.x;

    const float* gi = gin + (size_t)g * CIN * LIN;
    for (int i = tid; i < CIN * LIN; i += 256) s_in[i] = gi[i];
    for (int i = tid; i < CIN * 300; i += 256) {
        int co = i / (CIN * 3); int rem = i - co * (CIN * 3); // rem = ci*3+k
        s_w[rem * 100 + co] = gw[i];
    }
    if (tid < 100) s_b[tid] = gb[tid];
    __syncthreads();

    const int NP = (LPOOL + 1) / 2;
    for (int item = tid; item < 25 * NP; item += 256) {
        int cgi = item / NP, ppi = item - cgi * NP;
        int c0 = cgi * 4;
        int p0 = 2 * ppi;
        int qs = 3 * p0 - PPAD;   // first conv position of the 6 computed
        int t0 = qs - 1;          // first input position touched
        int off[8]; float mk[8];
#pragma unroll
        for (int j = 0; j < 8; j++) {
            int t = t0 + j; bool v = (t >= 0) && (t < LIN);
            off[j] = v ? t : 0; mk[j] = v ? 1.f : 0.f;
        }
        float2 aA[6], aB[6];
#pragma unroll
        for (int j = 0; j < 6; j++) { aA[j] = make_float2(0.f, 0.f); aB[j] = make_float2(0.f, 0.f); }

        const float4* wq = reinterpret_cast<const float4*>(s_w) + cgi;
#pragma unroll 2
        for (int ci = 0; ci < CIN; ci++) {
            const float* xr = s_in + ci * LIN;
            float2 xb[8];
#pragma unroll
            for (int j = 0; j < 8; j++) {
                float x = xr[off[j]] * mk[j];
                xb[j] = make_float2(x, x);
            }
            const float4* wr = wq + ci * 75;            // (ci*3+k)*25 + cgi
            float4 w0 = wr[0], w1 = wr[25], w2 = wr[50];
            float2 wA0 = make_float2(w0.x, w0.y), wB0 = make_float2(w0.z, w0.w);
            float2 wA1 = make_float2(w1.x, w1.y), wB1 = make_float2(w1.z, w1.w);
            float2 wA2 = make_float2(w2.x, w2.y), wB2 = make_float2(w2.z, w2.w);
#pragma unroll
            for (int j = 0; j < 6; j++) {
                aA[j] = ffma2(xb[j],     wA0, aA[j]); aB[j] = ffma2(xb[j],     wB0, aB[j]);
                aA[j] = ffma2(xb[j + 1], wA1, aA[j]); aB[j] = ffma2(xb[j + 1], wB1, aB[j]);
                aA[j] = ffma2(xb[j + 2], wA2, aA[j]); aB[j] = ffma2(xb[j + 2], wB2, aB[j]);
            }
        }
        float b0 = s_b[c0], b1 = s_b[c0 + 1], b2 = s_b[c0 + 2], b3 = s_b[c0 + 3];
        float* orow = gout + (size_t)g * OPITCH + c0 * LPOOL;
#pragma unroll
        for (int pp = 0; pp < 2; pp++) {
            int p = p0 + pp;
            if (p < LPOOL) {
                float m0 = -1e30f, m1 = -1e30f, m2 = -1e30f, m3 = -1e30f;
#pragma unroll
                for (int jj = 0; jj < 3; jj++) {
                    int j = pp * 3 + jj;
                    int q = qs + j;
                    if (q >= 0 && q < LIN) {
                        float v;
                        v = aA[j].x + b0; v = v > 0.f ? v : 0.01f * v; m0 = fmaxf(m0, v);
                        v = aA[j].y + b1; v = v > 0.f ? v : 0.01f * v; m1 = fmaxf(m1, v);
                        v = aB[j].x + b2; v = v > 0.f ? v : 0.01f * v; m2 = fmaxf(m2, v);
                        v = aB[j].y + b3; v = v > 0.f ? v : 0.01f * v; m3 = fmaxf(m3, v);
                    }
                }
                orow[0 * LPOOL + p] = m0;
                orow[1 * LPOOL + p] = m1;
                orow[2 * LPOOL + p] = m2;
                orow[3 * LPOOL + p] = m3;
            }
        }
    }
}

// ---------------- BN stats over z [2048, 900] ----------------
__global__ void __launch_bounds__(256) bnstat_k() {
    int b = blockIdx.x, tid = threadIdx.x;
    float s0 = 0, q0 = 0, s1 = 0, q1 = 0, s2 = 0, q2 = 0, s3 = 0, q3 = 0;
    const float* zb = d_z + (size_t)b * 32 * 900;
    for (int r = 0; r < 32; r++) {
        const float* zr = zb + r * 900;
        float v;
        v = zr[tid];       s0 += v; q0 += v * v;
        v = zr[tid + 256]; s1 += v; q1 += v * v;
        v = zr[tid + 512]; s2 += v; q2 += v * v;
        if (tid < 132) { v = zr[tid + 768]; s3 += v; q3 += v * v; }
    }
    atomicAdd(&d_bnsum[tid], s0);       atomicAdd(&d_bnsum[900 + tid], q0);
    atomicAdd(&d_bnsum[tid + 256], s1); atomicAdd(&d_bnsum[900 + tid + 256], q1);
    atomicAdd(&d_bnsum[tid + 512], s2); atomicAdd(&d_bnsum[900 + tid + 512], q2);
    if (tid < 132) { atomicAdd(&d_bnsum[tid + 768], s3); atomicAdd(&d_bnsum[900 + tid + 768], q3); }
}

__global__ void __launch_bounds__(256) bnfin_k(const float* __restrict__ bng,
                                               const float* __restrict__ bnb) {
    int c = blockIdx.x * 256 + threadIdx.x;
    if (c < 900) {
        float mu = d_bnsum[c] * (1.f / 2048.f);
        float var = d_bnsum[900 + c] * (1.f / 2048.f) - mu * mu;
        float s = bng[c] * rsqrtf(var + 1e-5f);
        d_sc[c] = s;
        d_sc[900 + c] = bnb[c] - mu * s;
    }
}

// Fold BN into fc1: W1p[j][i] = W1[i][j]*s[j]  (also transposes for coalesced GEMM loads)
__global__ void __launch_bounds__(256) foldw_k(const float* __restrict__ f1w) {
    int j = blockIdx.x, i = threadIdx.x;
    d_W1p[j * 256 + i] = f1w[(size_t)i * 900 + j] * d_sc[j];
}
__global__ void __launch_bounds__(256) foldb_k(const float* __restrict__ f1w,
                                               const float* __restrict__ f1b) {
    int i = threadIdx.x;
    float acc = f1b[i];
    for (int j = 0; j < 900; j++) acc += f1w[(size_t)i * 900 + j] * d_sc[900 + j];
    d_b1p[i] = acc;
}

// ---------------- fc1: relu(z @ W1p + b1p)  [2048,900]x[900,256] ----------------
__global__ void __launch_bounds__(256) fc1_k() {
    extern __shared__ float shm[]; // 16*900
    int b = blockIdx.x, tid = threadIdx.x;
    const float* zsrc = d_z + (size_t)b * 14400;
    for (int i = tid; i < 14400; i += 256) shm[i] = zsrc[i];
    __syncthreads();
    float2 acc[8];
#pragma unroll
    for (int r = 0; r < 8; r++) acc[r] = make_float2(0.f, 0.f);
    for (int j = 0; j < 900; j++) {
        float w = d_W1p[j * 256 + tid];
        float2 wv = make_float2(w, w);
#pragma unroll
        for (int rp = 0; rp < 8; rp++) {
            float2 xz = make_float2(shm[(2 * rp) * 900 + j], shm[(2 * rp + 1) * 900 + j]);
            acc[rp] = ffma2(xz, wv, acc[rp]);
        }
    }
    float bb = d_b1p[tid];
#pragma unroll
    for (int rp = 0; rp < 8; rp++) {
        d_o1[((size_t)b * 16 + 2 * rp) * 256 + tid]     = fmaxf(acc[rp].x + bb, 0.f);
        d_o1[((size_t)b * 16 + 2 * rp + 1) * 256 + tid] = fmaxf(acc[rp].y + bb, 0.f);
    }
}

// ---------------- fc2: relu(o1 @ W2^T + b2)  [2048,256]x[256,64] ----------------
__global__ void __launch_bounds__(256) fc2_k(const float* __restrict__ f2w,
                                             const float* __restrict__ f2b) {
    extern __shared__ float shm[];
    float* so = shm;          // 32*256
    float* sw = shm + 8192;   // 256*64 transposed [j][col]
    int b = blockIdx.x, tid = threadIdx.x;
    const float* osrc = d_o1 + (size_t)b * 8192;
    for (int i = tid; i < 8192; i += 256) so[i] = osrc[i];
    for (int d = tid; d < 16384; d += 256) {
        int j = d >> 6, c = d & 63;
        sw[d] = f2w[c * 256 + j];
    }
    __syncthreads();
    int col = tid & 63, rs = tid >> 6;
    float acc[8];
#pragma unroll
    for (int r = 0; r < 8; r++) acc[r] = 0.f;
    for (int j = 0; j < 256; j++) {
        float w = sw[j * 64 + col];
#pragma unroll
        for (int r = 0; r < 8; r++) acc[r] += so[(rs * 8 + r) * 256 + j] * w;
    }
    float bb = f2b[col];
#pragma unroll
    for (int r = 0; r < 8; r++)
        d_o2[((size_t)b * 32 + rs * 8 + r) * 64 + col] = fmaxf(acc[r] + bb, 0.f);
}

// ---------------- fc3: o2 @ W3^T + b3 -> out [2048,2] ----------------
__global__ void __launch_bounds__(256) fc3_k(const float* __restrict__ f3w,
                                             const float* __restrict__ f3b,
                                             float* __restrict__ out) {
    extern __shared__ float shm[]; // 256*65 (padded vs bank conflicts)
    int b = blockIdx.x, tid = threadIdx.x;
    const float* osrc = d_o2 + (size_t)b * 16384;
    for (int idx = tid; idx < 16384; idx += 256) {
        int r = idx >> 6, c = idx & 63;
        shm[r * 65 + c] = osrc[idx];
    }
    __syncthreads();
    float a0 = f3b[0], a1 = f3b[1];
    const float* row = shm + tid * 65;
    for (int j = 0; j < 64; j++) {
        float v = row[j];
        a0 += v * f3w[j];
        a1 += v * f3w[64 + j];
    }
    out[((size_t)b * 256 + tid) * 2]     = a0;
    out[((size_t)b * 256 + tid) * 2 + 1] = a1;
}

// ---------------- launch ----------------
extern "C" void kernel_launch(void* const* d_in, const int* in_sizes, int n_in,
                              void* d_out, int out_size) {
    const float* x1  = (const float*)d_in[0];
    const float* x2  = (const float*)d_in[1];
    const int*   ei  = (const int*)d_in[2];
    const float* Wl  = (const float*)d_in[4];
    const float* bl  = (const float*)d_in[5];
    const float* Wr  = (const float*)d_in[6];
    const float* cw1 = (const float*)d_in[7];  const float* cb1 = (const float*)d_in[8];
    const float* cw2 = (const float*)d_in[9];  const float* cb2 = (const float*)d_in[10];
    const float* cw3 = (const float*)d_in[11]; const float* cb3 = (const float*)d_in[12];
    const float* cw4 = (const float*)d_in[13]; const float* cb4 = (const float*)d_in[14];
    const float* bng = (const float*)d_in[15]; const float* bnb = (const float*)d_in[16];
    const float* f1w = (const float*)d_in[17]; const float* f1b = (const float*)d_in[18];
    const float* f2w = (const float*)d_in[19]; const float* f2b = (const float*)d_in[20];
    const float* f3w = (const float*)d_in[21]; const float* f3b = (const float*)d_in[22];
    float* out = (float*)d_out;
    int nE = in_sizes[2] / 2;

    float *p_s1, *p_s2, *p_s3, *p_z;
    cudaGetSymbolAddress((void**)&p_s1, d_s1);
    cudaGetSymbolAddress((void**)&p_s2, d_s2);
    cudaGetSymbolAddress((void**)&p_s3, d_s3);
    cudaGetSymbolAddress((void**)&p_z,  d_z);

    const int sm1 = (21 * 600 + 21 * 300 + 104) * 4;   //  76 KB
    const int sm2 = (100 * 200 + 100 * 300 + 104) * 4; // 200 KB
    const int sm3 = (100 * 67 + 100 * 300 + 104) * 4;  // 147 KB
    const int sm4 = (100 * 23 + 100 * 300 + 104) * 4;  // 130 KB
    cudaFuncSetAttribute(conv_k<21, 600, 200, 0, 20000>, cudaFuncAttributeMaxDynamicSharedMemorySize, sm1);
    cudaFuncSetAttribute(conv_k<100, 200, 67, 1, 6700>,  cudaFuncAttributeMaxDynamicSharedMemorySize, sm2);
    cudaFuncSetAttribute(conv_k<100, 67, 23, 1, 2300>,   cudaFuncAttributeMaxDynamicSharedMemorySize, sm3);
    cudaFuncSetAttribute(conv_k<100, 23, 8, 1, 900>,     cudaFuncAttributeMaxDynamicSharedMemorySize, sm4);
    cudaFuncSetAttribute(fc1_k, cudaFuncAttributeMaxDynamicSharedMemorySize, 57600);
    cudaFuncSetAttribute(fc2_k, cudaFuncAttributeMaxDynamicSharedMemorySize, 98304);
    cudaFuncSetAttribute(fc3_k, cudaFuncAttributeMaxDynamicSharedMemorySize, 66560);

    zero_k<<<5120, 256>>>();
    edge_k<<<(nE + 255) / 256, 256>>>(x1, ei, nE);
    gpool_k<<<2048, 128>>>(x1, Wl, bl, Wr);
    conv_k<21, 600, 200, 0, 20000><<<2048, 256, sm1>>>(x2, cw1, cb1, p_s1);
    conv_k<100, 200, 67, 1, 6700><<<2048, 256, sm2>>>(p_s1, cw2, cb2, p_s2);
    conv_k<100, 67, 23, 1, 2300><<<2048, 256, sm3>>>(p_s2, cw3, cb3, p_s3);
    conv_k<100, 23, 8, 1, 900><<<2048, 256, sm4>>>(p_s3, cw4, cb4, p_z + 100);
    bnstat_k<<<64, 256>>>();
    bnfin_k<<<4, 256>>>(bng, bnb);
    foldw_k<<<900, 256>>>(f1w);
    foldb_k<<<1, 256>>>(f1w, f1b);
    fc1_k<<<128, 256, 57600>>>();
    fc2_k<<<64, 256, 98304>>>(f2w, f2b);
    fc3_k<<<8, 256, 66560>>>(f3w, f3b, out);
}

// round 4
// speedup vs baseline: 1.2315x; 1.2315x over previous
#include <cuda_runtime.h>
#include <cstring>

#define N_NODES   131072
#define N_GRAPHS  2048

// ---------------- scratch (static device globals; no allocs) ----------------
__device__ float d_msg[N_NODES * 10];
__device__ float d_deg[N_NODES];
__device__ float d_z[N_GRAPHS * 900];
__device__ float d_s1[N_GRAPHS * 100 * 200];
__device__ float d_s2[N_GRAPHS * 100 * 67];
__device__ float d_s3[N_GRAPHS * 100 * 23];
__device__ float d_bnsum[1800];
__device__ float d_sc[1800];       // [0..899]=scale, [900..1799]=shift
__device__ float d_W1p[900 * 256]; // folded fc1 weights, [j][i] transposed
__device__ float d_b1p[256];
__device__ float d_o1[N_GRAPHS * 256];
__device__ float d_o2[N_GRAPHS * 64];

// packed f32x2 FMA (Blackwell FFMA2; 2x fp32 throughput vs 3-reg FFMA)
__device__ __forceinline__ float2 ffma2(float2 a, float2 b, float2 c) {
    unsigned long long au, bu, cu, du;
    memcpy(&au, &a, 8); memcpy(&bu, &b, 8); memcpy(&cu, &c, 8);
    asm("fma.rn.f32x2 %0, %1, %2, %3;" : "=l"(du) : "l"(au), "l"(bu), "l"(cu));
    float2 d; memcpy(&d, &du, 8); return d;
}

// ---------------- zero scratch ----------------
__global__ void __launch_bounds__(256) zero_k() {
    unsigned int i = blockIdx.x * 256u + threadIdx.x;
    if (i < N_NODES * 10) d_msg[i] = 0.f;
    if (i < N_NODES)      d_deg[i] = 0.f;
    if (i < 1800)         d_bnsum[i] = 0.f;
}

// ---------------- edge scatter: msg_sum[dst] += x1[src], deg[dst] += 1 ----------------
__global__ void __launch_bounds__(256) edge_k(const float* __restrict__ x1,
                                              const int* __restrict__ ei, int nE) {
    int e = blockIdx.x * 256 + threadIdx.x;
    if (e >= nE) return;
    int s = ei[e], d = ei[nE + e];
    atomicAdd(&d_deg[d], 1.f);
    const float2* xs = (const float2*)(x1 + (size_t)s * 10);
    float* m = d_msg + (size_t)d * 10;
#pragma unroll
    for (int f = 0; f < 5; f++) {
        float2 v = xs[f];
        atomicAdd(&m[2 * f], v.x);
        atomicAdd(&m[2 * f + 1], v.y);
    }
}

// ---------------- graph branch: per-graph sums, then tiny GEMV into z[:, 0:100] ----------
__global__ void __launch_bounds__(128) gpool_k(const float* __restrict__ x1,
                                               const float* __restrict__ Wl,
                                               const float* __restrict__ bl,
                                               const float* __restrict__ Wr) {
    __shared__ float sm_[10], sx_[10];
    int g = blockIdx.x, tid = threadIdx.x;
    if (tid < 10) { sm_[tid] = 0.f; sx_[tid] = 0.f; }
    __syncthreads();
    if (tid < 64) {
        int n = g * 64 + tid;
        float inv = 1.f / fmaxf(d_deg[n], 1.f);
#pragma unroll
        for (int f = 0; f < 10; f++) {
            atomicAdd(&sm_[f], d_msg[(size_t)n * 10 + f] * inv);
            atomicAdd(&sx_[f], x1[(size_t)n * 10 + f]);
        }
    }
    __syncthreads();
    if (tid < 100) {
        float acc = 64.f * bl[tid];
#pragma unroll
        for (int f = 0; f < 10; f++)
            acc += sm_[f] * Wl[tid * 10 + f] + sx_[f] * Wr[tid * 10 + f];
        d_z[(size_t)g * 900 + tid] = acc;
    }
}

// ---------------- fused conv1d(same,k=3) + leakyReLU + maxpool3(stride3) ----------------
// Item = 8 out-channels x 2 pooled positions (halves x-LDS per FMA vs 4-co).
// Input rows zero-padded (+2 left, right to LINP) in smem -> no boundary masks,
// x loaded as 5 aligned float2 (conflict-free). Weights transposed [ci*3+k][co]
// padded to 104 co so LDS.128 yields 4-channel quads. NG graphs per block.
template <int CIN, int LIN, int LINP, int LPOOL, int PPAD, int NG, int OPITCH>
__global__ void __launch_bounds__(256) conv_k(const float* __restrict__ gin,
                                              const float* __restrict__ gw,
                                              const float* __restrict__ gb,
                                              float* __restrict__ gout) {
    extern __shared__ float shm[];
    float* s_in = shm;                         // NG*CIN*LINP
    float* s_w  = shm + NG * CIN * LINP;       // CIN*3*104 (transposed, padded)
    float* s_b  = s_w + CIN * 312;             // 104
    const int tid = threadIdx.x;
    const int g0 = blockIdx.x * NG;

    const int TOT = NG * CIN * LINP + CIN * 312 + 104;
    for (int i = tid; i < TOT; i += 256) shm[i] = 0.f;
    __syncthreads();

#pragma unroll
    for (int gg = 0; gg < NG; gg++) {
        const float* gi = gin + (size_t)(g0 + gg) * CIN * LIN;
        float* si = s_in + gg * CIN * LINP;
        for (int i = tid; i < CIN * LIN; i += 256) {
            int ci = i / LIN, t = i - ci * LIN;
            si[ci * LINP + 2 + t] = gi[i];
        }
    }
    for (int i = tid; i < CIN * 300; i += 256) {
        int co = i / (CIN * 3); int rem = i - co * (CIN * 3); // rem = ci*3+k
        s_w[rem * 104 + co] = gw[i];
    }
    if (tid < 100) s_b[tid] = gb[tid];
    __syncthreads();

    const int NP = (LPOOL + 1) / 2;
    const int NI = NG * 13 * NP;
    for (int item = tid; item < NI; item += 256) {
        int gg = item / (13 * NP);
        int rest = item - gg * (13 * NP);
        int cgi = rest / NP, ppi = rest - cgi * NP;
        int c0 = cgi * 8;
        int p0 = 2 * ppi;
        int qs = 3 * p0 - PPAD;   // first conv position of the 6 computed
        int t0 = qs - 1;          // first input position touched
        int e0 = t0 & ~1;         // aligned even base
        bool dd = (t0 & 1) != 0;
        const float* sbase = s_in + gg * CIN * LINP + 2 + e0;

        float2 ac[4][6];
#pragma unroll
        for (int p = 0; p < 4; p++)
#pragma unroll
            for (int j = 0; j < 6; j++) ac[p][j] = make_float2(0.f, 0.f);

#pragma unroll 2
        for (int ci = 0; ci < CIN; ci++) {
            const float2* xr = reinterpret_cast<const float2*>(sbase + ci * LINP);
            float2 v0 = xr[0], v1 = xr[1], v2 = xr[2], v3 = xr[3], v4 = xr[4];
            float vv[10] = {v0.x, v0.y, v1.x, v1.y, v2.x, v2.y, v3.x, v3.y, v4.x, v4.y};
            float xs[8];
#pragma unroll
            for (int j = 0; j < 8; j++) xs[j] = dd ? vv[j + 1] : vv[j];

            const float4* wr = reinterpret_cast<const float4*>(s_w) + ci * 78 + 2 * cgi;
            float4 q0 = wr[0], q1 = wr[1], q2 = wr[26], q3 = wr[27], q4 = wr[52], q5 = wr[53];
            float2 w2[3][4] = {
                {{q0.x, q0.y}, {q0.z, q0.w}, {q1.x, q1.y}, {q1.z, q1.w}},
                {{q2.x, q2.y}, {q2.z, q2.w}, {q3.x, q3.y}, {q3.z, q3.w}},
                {{q4.x, q4.y}, {q4.z, q4.w}, {q5.x, q5.y}, {q5.z, q5.w}}};
#pragma unroll
            for (int j = 0; j < 6; j++) {
#pragma unroll
                for (int k = 0; k < 3; k++) {
                    float2 xsp = make_float2(xs[j + k], xs[j + k]);
#pragma unroll
                    for (int p = 0; p < 4; p++)
                        ac[p][j] = ffma2(xsp, w2[k][p], ac[p][j]);
                }
            }
        }

        float bs[8];
#pragma unroll
        for (int cc = 0; cc < 8; cc++) bs[cc] = s_b[c0 + cc];
        float* og = gout + (size_t)(g0 + gg) * OPITCH + c0 * LPOOL;
#pragma unroll
        for (int pp = 0; pp < 2; pp++) {
            int p = p0 + pp;
            if (p < LPOOL) {
                float m[8];
#pragma unroll
                for (int cc = 0; cc < 8; cc++) m[cc] = -1e30f;
#pragma unroll
                for (int jj = 0; jj < 3; jj++) {
                    int j = pp * 3 + jj;
                    int q = qs + j;
                    if (q >= 0 && q < LIN) {
#pragma unroll
                        for (int cc = 0; cc < 8; cc++) {
                            float v = ((cc & 1) ? ac[cc >> 1][j].y : ac[cc >> 1][j].x) + bs[cc];
                            v = v > 0.f ? v : 0.01f * v;
                            m[cc] = fmaxf(m[cc], v);
                        }
                    }
                }
#pragma unroll
                for (int cc = 0; cc < 8; cc++)
                    if (c0 + cc < 100) og[cc * LPOOL + p] = m[cc];
            }
        }
    }
}

// ---------------- BN stats over z [2048, 900] ----------------
__global__ void __launch_bounds__(256) bnstat_k() {
    int b = blockIdx.x, tid = threadIdx.x;
    float s0 = 0, q0 = 0, s1 = 0, q1 = 0, s2 = 0, q2 = 0, s3 = 0, q3 = 0;
    const float* zb = d_z + (size_t)b * 32 * 900;
    for (int r = 0; r < 32; r++) {
        const float* zr = zb + r * 900;
        float v;
        v = zr[tid];       s0 += v; q0 += v * v;
        v = zr[tid + 256]; s1 += v; q1 += v * v;
        v = zr[tid + 512]; s2 += v; q2 += v * v;
        if (tid < 132) { v = zr[tid + 768]; s3 += v; q3 += v * v; }
    }
    atomicAdd(&d_bnsum[tid], s0);       atomicAdd(&d_bnsum[900 + tid], q0);
    atomicAdd(&d_bnsum[tid + 256], s1); atomicAdd(&d_bnsum[900 + tid + 256], q1);
    atomicAdd(&d_bnsum[tid + 512], s2); atomicAdd(&d_bnsum[900 + tid + 512], q2);
    if (tid < 132) { atomicAdd(&d_bnsum[tid + 768], s3); atomicAdd(&d_bnsum[900 + tid + 768], q3); }
}

__global__ void __launch_bounds__(256) bnfin_k(const float* __restrict__ bng,
                                               const float* __restrict__ bnb) {
    int c = blockIdx.x * 256 + threadIdx.x;
    if (c < 900) {
        float mu = d_bnsum[c] * (1.f / 2048.f);
        float var = d_bnsum[900 + c] * (1.f / 2048.f) - mu * mu;
        float s = bng[c] * rsqrtf(var + 1e-5f);
        d_sc[c] = s;
        d_sc[900 + c] = bnb[c] - mu * s;
    }
}

// Fold BN into fc1: W1p[j][i] = W1[i][j]*s[j]  (transposed for coalesced loads)
__global__ void __launch_bounds__(256) foldw_k(const float* __restrict__ f1w) {
    int j = blockIdx.x, i = threadIdx.x;
    d_W1p[j * 256 + i] = f1w[(size_t)i * 900 + j] * d_sc[j];
}
// b1p[i] = f1b[i] + sum_j W1[i][j]*shift[j]  (UNSCALED W1 — scale lives in W1p only).
// One block per output i: coalesced row read + tree reduction.
__global__ void __launch_bounds__(256) foldb_k(const float* __restrict__ f1w,
                                               const float* __restrict__ f1b) {
    __shared__ float red[256];
    int i = blockIdx.x, tid = threadIdx.x;
    float acc = 0.f;
    for (int j = tid; j < 900; j += 256)
        acc += f1w[(size_t)i * 900 + j] * d_sc[900 + j];
    red[tid] = acc;
    __syncthreads();
#pragma unroll
    for (int s = 128; s > 0; s >>= 1) {
        if (tid < s) red[tid] += red[tid + s];
        __syncthreads();
    }
    if (tid == 0) d_b1p[i] = red[0] + f1b[i];
}

// ---------------- fc1: relu(z @ W1p + b1p)  [2048,900]x[900,256] ----------------
__global__ void __launch_bounds__(256) fc1_k() {
    extern __shared__ float shm[]; // 16*900
    int b = blockIdx.x, tid = threadIdx.x;
    const float* zsrc = d_z + (size_t)b * 14400;
    for (int i = tid; i < 14400; i += 256) shm[i] = zsrc[i];
    __syncthreads();
    float2 acc[8];
#pragma unroll
    for (int r = 0; r < 8; r++) acc[r] = make_float2(0.f, 0.f);
    for (int j = 0; j < 900; j++) {
        float w = d_W1p[j * 256 + tid];
        float2 wv = make_float2(w, w);
#pragma unroll
        for (int rp = 0; rp < 8; rp++) {
            float2 xz = make_float2(shm[(2 * rp) * 900 + j], shm[(2 * rp + 1) * 900 + j]);
            acc[rp] = ffma2(xz, wv, acc[rp]);
        }
    }
    float bb = d_b1p[tid];
#pragma unroll
    for (int rp = 0; rp < 8; rp++) {
        d_o1[((size_t)b * 16 + 2 * rp) * 256 + tid]     = fmaxf(acc[rp].x + bb, 0.f);
        d_o1[((size_t)b * 16 + 2 * rp + 1) * 256 + tid] = fmaxf(acc[rp].y + bb, 0.f);
    }
}

// ---------------- fc2: relu(o1 @ W2^T + b2)  [2048,256]x[256,64] ----------------
__global__ void __launch_bounds__(256) fc2_k(const float* __restrict__ f2w,
                                             const float* __restrict__ f2b) {
    extern __shared__ float shm[];
    float* so = shm;          // 32*256
    float* sw = shm + 8192;   // 256*64 transposed [j][col]
    int b = blockIdx.x, tid = threadIdx.x;
    const float* osrc = d_o1 + (size_t)b * 8192;
    for (int i = tid; i < 8192; i += 256) so[i] = osrc[i];
    for (int d = tid; d < 16384; d += 256) {
        int j = d >> 6, c = d & 63;
        sw[d] = f2w[c * 256 + j];
    }
    __syncthreads();
    int col = tid & 63, rs = tid >> 6;
    float acc[8];
#pragma unroll
    for (int r = 0; r < 8; r++) acc[r] = 0.f;
    for (int j = 0; j < 256; j++) {
        float w = sw[j * 64 + col];
#pragma unroll
        for (int r = 0; r < 8; r++) acc[r] += so[(rs * 8 + r) * 256 + j] * w;
    }
    float bb = f2b[col];
#pragma unroll
    for (int r = 0; r < 8; r++)
        d_o2[((size_t)b * 32 + rs * 8 + r) * 64 + col] = fmaxf(acc[r] + bb, 0.f);
}

// ---------------- fc3: o2 @ W3^T + b3 -> out [2048,2] ----------------
__global__ void __launch_bounds__(256) fc3_k(const float* __restrict__ f3w,
                                             const float* __restrict__ f3b,
                                             float* __restrict__ out) {
    extern __shared__ float shm[]; // 256*65 (padded vs bank conflicts)
    int b = blockIdx.x, tid = threadIdx.x;
    const float* osrc = d_o2 + (size_t)b * 16384;
    for (int idx = tid; idx < 16384; idx += 256) {
        int r = idx >> 6, c = idx & 63;
        shm[r * 65 + c] = osrc[idx];
    }
    __syncthreads();
    float a0 = f3b[0], a1 = f3b[1];
    const float* row = shm + tid * 65;
    for (int j = 0; j < 64; j++) {
        float v = row[j];
        a0 += v * f3w[j];
        a1 += v * f3w[64 + j];
    }
    out[((size_t)b * 256 + tid) * 2]     = a0;
    out[((size_t)b * 256 + tid) * 2 + 1] = a1;
}

// ---------------- launch ----------------
extern "C" void kernel_launch(void* const* d_in, const int* in_sizes, int n_in,
                              void* d_out, int out_size) {
    const float* x1  = (const float*)d_in[0];
    const float* x2  = (const float*)d_in[1];
    const int*   ei  = (const int*)d_in[2];
    const float* Wl  = (const float*)d_in[4];
    const float* bl  = (const float*)d_in[5];
    const float* Wr  = (const float*)d_in[6];
    const float* cw1 = (const float*)d_in[7];  const float* cb1 = (const float*)d_in[8];
    const float* cw2 = (const float*)d_in[9];  const float* cb2 = (const float*)d_in[10];
    const float* cw3 = (const float*)d_in[11]; const float* cb3 = (const float*)d_in[12];
    const float* cw4 = (const float*)d_in[13]; const float* cb4 = (const float*)d_in[14];
    const float* bng = (const float*)d_in[15]; const float* bnb = (const float*)d_in[16];
    const float* f1w = (const float*)d_in[17]; const float* f1b = (const float*)d_in[18];
    const float* f2w = (const float*)d_in[19]; const float* f2b = (const float*)d_in[20];
    const float* f3w = (const float*)d_in[21]; const float* f3b = (const float*)d_in[22];
    float* out = (float*)d_out;
    int nE = in_sizes[2] / 2;

    float *p_s1, *p_s2, *p_s3, *p_z;
    cudaGetSymbolAddress((void**)&p_s1, d_s1);
    cudaGetSymbolAddress((void**)&p_s2, d_s2);
    cudaGetSymbolAddress((void**)&p_s3, d_s3);
    cudaGetSymbolAddress((void**)&p_z,  d_z);

    const int sm1 = (1 * 21 * 616 + 21 * 312 + 104) * 4;    //  78.4 KB (2 CTA/SM)
    const int sm2 = (1 * 100 * 216 + 100 * 312 + 104) * 4;  // 211.6 KB
    const int sm3 = (2 * 100 * 84 + 100 * 312 + 104) * 4;   // 192.4 KB
    const int sm4 = (4 * 100 * 40 + 100 * 312 + 104) * 4;   // 189.2 KB
    cudaFuncSetAttribute(conv_k<21, 600, 616, 200, 0, 1, 20000>, cudaFuncAttributeMaxDynamicSharedMemorySize, sm1);
    cudaFuncSetAttribute(conv_k<100, 200, 216, 67, 1, 1, 6700>,  cudaFuncAttributeMaxDynamicSharedMemorySize, sm2);
    cudaFuncSetAttribute(conv_k<100, 67, 84, 23, 1, 2, 2300>,    cudaFuncAttributeMaxDynamicSharedMemorySize, sm3);
    cudaFuncSetAttribute(conv_k<100, 23, 40, 8, 1, 4, 900>,      cudaFuncAttributeMaxDynamicSharedMemorySize, sm4);
    cudaFuncSetAttribute(fc1_k, cudaFuncAttributeMaxDynamicSharedMemorySize, 57600);
    cudaFuncSetAttribute(fc2_k, cudaFuncAttributeMaxDynamicSharedMemorySize, 98304);
    cudaFuncSetAttribute(fc3_k, cudaFuncAttributeMaxDynamicSharedMemorySize, 66560);

    zero_k<<<5120, 256>>>();
    edge_k<<<(nE + 255) / 256, 256>>>(x1, ei, nE);
    gpool_k<<<2048, 128>>>(x1, Wl, bl, Wr);
    conv_k<21, 600, 616, 200, 0, 1, 20000><<<2048, 256, sm1>>>(x2, cw1, cb1, p_s1);
    conv_k<100, 200, 216, 67, 1, 1, 6700><<<2048, 256, sm2>>>(p_s1, cw2, cb2, p_s2);
    conv_k<100, 67, 84, 23, 1, 2, 2300><<<1024, 256, sm3>>>(p_s2, cw3, cb3, p_s3);
    conv_k<100, 23, 40, 8, 1, 4, 900><<<512, 256, sm4>>>(p_s3, cw4, cb4, p_z + 100);
    bnstat_k<<<64, 256>>>();
    bnfin_k<<<4, 256>>>(bng, bnb);
    foldw_k<<<900, 256>>>(f1w);
    foldb_k<<<256, 256>>>(f1w, f1b);
    fc1_k<<<128, 256, 57600>>>();
    fc2_k<<<64, 256, 98304>>>(f2w, f2b);
    fc3_k<<<8, 256, 66560>>>(f3w, f3b, out);
}